// round 3
// baseline (speedup 1.0000x reference)
#include <cuda_runtime.h>
#include <cuda_bf16.h>
#include <math.h>

// ---------------------------------------------------------------------------
// Problem constants (match reference generator)
// ---------------------------------------------------------------------------
#define NMAX   100000
#define EMAX   1600000
#define EPMAX  (EMAX + NMAX)
#define GMAX   256
#define HID    64

// ---------------------------------------------------------------------------
// Scratch (device globals; no allocation allowed)
// ---------------------------------------------------------------------------
__device__ __align__(16) float    g_h[(size_t)NMAX * 128];   // h = A @ W   [N, 2*64]
__device__ __align__(16) float    g_agg[(size_t)NMAX * 64];  // msg accum   [N, 64]
__device__ __align__(16) float    g_out1[(size_t)NMAX * 64]; // layer out   [N, 64]
__device__ __align__(16) float    g_asrc[NMAX * 2];
__device__ __align__(16) float    g_adst[NMAX * 2];
__device__ __align__(16) unsigned g_mmax[NMAX * 2];          // encoded float max
__device__ __align__(16) float    g_denom[NMAX * 2];
__device__ __align__(16) float    g_evals[(size_t)EPMAX * 2];
__device__ __align__(16) float    g_pool[GMAX * 64];
__device__ float                  g_cnt[GMAX];
__device__ int                    g_gstart[GMAX];

// ---------------------------------------------------------------------------
// Orderable-uint encoding for float atomic max
// ---------------------------------------------------------------------------
__device__ __forceinline__ unsigned fenc(float x) {
    unsigned u = __float_as_uint(x);
    return (u & 0x80000000u) ? ~u : (u | 0x80000000u);
}
__device__ __forceinline__ float fdec(unsigned u) {
    return (u & 0x80000000u) ? __uint_as_float(u & 0x7FFFFFFFu)
                             : __uint_as_float(~u);
}

// ---------------------------------------------------------------------------
// Per-layer init: zero agg, mmax, denom
// ---------------------------------------------------------------------------
__global__ void init_layer_kernel(int n) {
    int total = n * 64;
    for (int i = blockIdx.x * blockDim.x + threadIdx.x; i < total;
         i += gridDim.x * blockDim.x) {
        g_agg[i] = 0.0f;
        if (i < n * 2) { g_mmax[i] = 0u; g_denom[i] = 0.0f; }
    }
}

// ---------------------------------------------------------------------------
// Tiled GEMM: g_h[n,128] = A[n,K] @ W[K,128]
// A = external pointer (layer 1) or g_out1 (layer 2), chosen at compile time.
// block = 256 threads, 64-row tile, 32-k chunks, <=24KB static smem
// ---------------------------------------------------------------------------
template <int K, bool FROM_GLOBAL>
__global__ void gemm_kernel(const float* __restrict__ Ain,
                            const float* __restrict__ W, int n) {
    const float* __restrict__ A = FROM_GLOBAL ? (const float*)g_out1 : Ain;
    __shared__ __align__(16) float As[64 * 32];
    __shared__ __align__(16) float Ws[32 * 128];
    const int tid = threadIdx.x;
    const int q  = tid & 31;   // column quad -> cols 4q..4q+3
    const int rg = tid >> 5;   // row group   -> rows rg*8..rg*8+7

    const int tile = blockIdx.x * 64;
    if (tile >= n) return;

    float acc[8][4];
#pragma unroll
    for (int r = 0; r < 8; r++)
#pragma unroll
        for (int c = 0; c < 4; c++) acc[r][c] = 0.0f;

    for (int kk = 0; kk < K; kk += 32) {
        __syncthreads();
#pragma unroll
        for (int i = tid; i < 64 * 32; i += 256) {
            int r = i >> 5, c = i & 31;
            int row = tile + r;
            As[i] = (row < n) ? A[(size_t)row * K + kk + c] : 0.0f;
        }
#pragma unroll
        for (int i = tid; i < 32 * 128; i += 256) {
            Ws[i] = W[(size_t)(kk + (i >> 7)) * 128 + (i & 127)];
        }
        __syncthreads();
#pragma unroll
        for (int k = 0; k < 32; k++) {
            float4 w = *(const float4*)&Ws[k * 128 + q * 4];
#pragma unroll
            for (int r = 0; r < 8; r++) {
                float a = As[(rg * 8 + r) * 32 + k];
                acc[r][0] += a * w.x;
                acc[r][1] += a * w.y;
                acc[r][2] += a * w.z;
                acc[r][3] += a * w.w;
            }
        }
    }
#pragma unroll
    for (int r = 0; r < 8; r++) {
        int row = tile + rg * 8 + r;
        if (row < n) {
            float4 v = make_float4(acc[r][0], acc[r][1], acc[r][2], acc[r][3]);
            *(float4*)&g_h[(size_t)row * 128 + q * 4] = v;
        }
    }
}

// ---------------------------------------------------------------------------
// Attention coefficients: asrc[n,h], adst[n,h] = sum_f h[n,h,f]*att[h,f]
// warp per node
// ---------------------------------------------------------------------------
__global__ void att_kernel(const float* __restrict__ attS,
                           const float* __restrict__ attD, int n) {
    int w = (blockIdx.x * blockDim.x + threadIdx.x) >> 5;
    if (w >= n) return;
    int lane = threadIdx.x & 31;
    const float* hr = g_h + (size_t)w * 128;

    float s0 = hr[lane] * attS[lane] + hr[lane + 32] * attS[lane + 32];
    float d0 = hr[lane] * attD[lane] + hr[lane + 32] * attD[lane + 32];
    float s1 = hr[64 + lane] * attS[64 + lane] + hr[96 + lane] * attS[96 + lane];
    float d1 = hr[64 + lane] * attD[64 + lane] + hr[96 + lane] * attD[96 + lane];
#pragma unroll
    for (int o = 16; o; o >>= 1) {
        s0 += __shfl_down_sync(0xFFFFFFFFu, s0, o);
        s1 += __shfl_down_sync(0xFFFFFFFFu, s1, o);
        d0 += __shfl_down_sync(0xFFFFFFFFu, d0, o);
        d1 += __shfl_down_sync(0xFFFFFFFFu, d1, o);
    }
    if (lane == 0) {
        g_asrc[w * 2] = s0; g_asrc[w * 2 + 1] = s1;
        g_adst[w * 2] = d0; g_adst[w * 2 + 1] = d1;
    }
}

// ---------------------------------------------------------------------------
// Edge pass A: e = leaky_relu(asrc[src]+adst[dst]); store; atomic max per dst
// edge_index is int32: src = ei[e], dst = ei[E + e]
// ---------------------------------------------------------------------------
__global__ void edgeA_kernel(const int* __restrict__ ei, int E, int ep) {
    int e = blockIdx.x * blockDim.x + threadIdx.x;
    if (e >= ep) return;
    int s, d;
    if (e < E) { s = ei[e]; d = ei[E + e]; }
    else       { s = e - E; d = e - E; }
    float2 as = *(const float2*)&g_asrc[s * 2];
    float2 ad = *(const float2*)&g_adst[d * 2];
    float e0 = as.x + ad.x;
    float e1 = as.y + ad.y;
    e0 = (e0 > 0.0f) ? e0 : 0.2f * e0;
    e1 = (e1 > 0.0f) ? e1 : 0.2f * e1;
    g_evals[(size_t)e * 2]     = e0;
    g_evals[(size_t)e * 2 + 1] = e1;
    atomicMax(&g_mmax[d * 2],     fenc(e0));
    atomicMax(&g_mmax[d * 2 + 1], fenc(e1));
}

// ---------------------------------------------------------------------------
// Edge pass B: ex = exp(e - max[dst]); store ex; atomic add denom[dst]
// ---------------------------------------------------------------------------
__global__ void edgeB_kernel(const int* __restrict__ ei, int E, int ep) {
    int e = blockIdx.x * blockDim.x + threadIdx.x;
    if (e >= ep) return;
    int d = (e < E) ? ei[E + e] : (e - E);
    float m0 = fdec(g_mmax[d * 2]);
    float m1 = fdec(g_mmax[d * 2 + 1]);
    float x0 = __expf(g_evals[(size_t)e * 2]     - m0);
    float x1 = __expf(g_evals[(size_t)e * 2 + 1] - m1);
    g_evals[(size_t)e * 2]     = x0;
    g_evals[(size_t)e * 2 + 1] = x1;
    atomicAdd(&g_denom[d * 2],     x0);
    atomicAdd(&g_denom[d * 2 + 1], x1);
}

// ---------------------------------------------------------------------------
// Edge pass C: warp per edge. agg[dst,f] += 0.5*(a0*h[src,f] + a1*h[src,64+f])
// (head-mean folded into the accumulation -> single [N,64] accumulator)
// ---------------------------------------------------------------------------
__global__ void edgeC_kernel(const int* __restrict__ ei, int E, int ep) {
    int e = (blockIdx.x * blockDim.x + threadIdx.x) >> 5;
    if (e >= ep) return;
    int lane = threadIdx.x & 31;
    int s, d;
    if (e < E) { s = ei[e]; d = ei[E + e]; }
    else       { s = e - E; d = e - E; }
    float a0 = g_evals[(size_t)e * 2]     / g_denom[d * 2];
    float a1 = g_evals[(size_t)e * 2 + 1] / g_denom[d * 2 + 1];
    a0 *= 0.5f; a1 *= 0.5f;
    int f = lane * 2;
    const float* hp = g_h + (size_t)s * 128;
    float2 hA = *(const float2*)(hp + f);
    float2 hB = *(const float2*)(hp + 64 + f);
    float vx = a0 * hA.x + a1 * hB.x;
    float vy = a0 * hA.y + a1 * hB.y;
    float* dst = g_agg + (size_t)d * 64 + f;
    asm volatile("red.global.add.v2.f32 [%0], {%1, %2};"
                 :: "l"(dst), "f"(vx), "f"(vy) : "memory");
}

// ---------------------------------------------------------------------------
// Finish layer: out = relu(agg + bias)
// ---------------------------------------------------------------------------
__global__ void finish_kernel(const float* __restrict__ bias, int n) {
    int total = n * 64;
    for (int i = blockIdx.x * blockDim.x + threadIdx.x; i < total;
         i += gridDim.x * blockDim.x) {
        float v = g_agg[i] + bias[i & 63];
        g_out1[i] = (v > 0.0f) ? v : 0.0f;
    }
}

// ---------------------------------------------------------------------------
// Pooling: batch is sorted -> contiguous graph ranges
// ---------------------------------------------------------------------------
__global__ void init_pool_kernel() {
    int t = threadIdx.x;
    if (t < GMAX) { g_cnt[t] = 0.0f; g_gstart[t] = 0x7FFFFFFF; }
}

__global__ void poolprep_kernel(const int* __restrict__ batch, int n) {
    int i = blockIdx.x * blockDim.x + threadIdx.x;
    if (i >= n) return;
    int b = batch[i];
    atomicAdd(&g_cnt[b], 1.0f);
    atomicMin(&g_gstart[b], i);
}

__global__ void poolsum_kernel(int n) {
    int g = blockIdx.x;          // 256 blocks
    int t = threadIdx.x;         // 64 threads (feature)
    float c   = g_cnt[g];
    int   cnt = (int)c;
    float a0 = 0.f, a1 = 0.f, a2 = 0.f, a3 = 0.f;
    if (cnt > 0) {
        int st = g_gstart[g];
        int i = 0;
        for (; i + 4 <= cnt; i += 4) {
            a0 += g_out1[(size_t)(st + i)     * 64 + t];
            a1 += g_out1[(size_t)(st + i + 1) * 64 + t];
            a2 += g_out1[(size_t)(st + i + 2) * 64 + t];
            a3 += g_out1[(size_t)(st + i + 3) * 64 + t];
        }
        for (; i < cnt; i++) a0 += g_out1[(size_t)(st + i) * 64 + t];
    }
    g_pool[g * 64 + t] = (a0 + a1 + a2 + a3) / fmaxf(c, 1.0f);
}

// ---------------------------------------------------------------------------
// Heads: three small matmuls + softmax per graph
// out layout: object [0,8192), goal [8192,12288), action [12288,14336)
// ---------------------------------------------------------------------------
__device__ void softmax_out(const float* l, int sz, float* o) {
    float m = -1e30f;
    for (int i = 0; i < sz; i++) m = fmaxf(m, l[i]);
    float s = 0.0f;
    for (int i = 0; i < sz; i++) s += expf(l[i] - m);
    float inv = 1.0f / s;
    for (int i = 0; i < sz; i++) o[i] = expf(l[i] - m) * inv;
}

__global__ void heads_kernel(const float* __restrict__ Wo, const float* __restrict__ bo,
                             const float* __restrict__ Wg, const float* __restrict__ bg,
                             const float* __restrict__ Wa, const float* __restrict__ ba,
                             float* __restrict__ out) {
    __shared__ float p[64];
    __shared__ float l[56];
    int g = blockIdx.x;
    int t = threadIdx.x;
    p[t] = g_pool[g * 64 + t];
    __syncthreads();
    if (t < 32) {
        float acc = bo[t];
        for (int k = 0; k < 64; k++) acc += p[k] * Wo[k * 32 + t];
        l[t] = acc;
    } else if (t < 48) {
        int j = t - 32;
        float acc = bg[j];
        for (int k = 0; k < 64; k++) acc += p[k] * Wg[k * 16 + j];
        l[32 + j] = acc;
    } else if (t < 56) {
        int j = t - 48;
        float acc = ba[j];
        for (int k = 0; k < 64; k++) acc += p[k] * Wa[k * 8 + j];
        l[48 + j] = acc;
    }
    __syncthreads();
    if (t == 0) softmax_out(l,      32, out + g * 32);
    if (t == 1) softmax_out(l + 32, 16, out + 8192  + g * 16);
    if (t == 2) softmax_out(l + 48, 8,  out + 12288 + g * 8);
}

// ---------------------------------------------------------------------------
// Host driver (graph-capturable: only kernel launches on default stream)
// NOTE: no __device__ symbol may be referenced from host code.
// ---------------------------------------------------------------------------
static void run_edge_phase(const float* attS, const float* attD,
                           const float* bias, const int* ei,
                           int n, int E, int ep) {
    att_kernel<<<((size_t)n * 32 + 255) / 256, 256>>>(attS, attD, n);
    edgeA_kernel<<<(ep + 255) / 256, 256>>>(ei, E, ep);
    edgeB_kernel<<<(ep + 255) / 256, 256>>>(ei, E, ep);
    edgeC_kernel<<<(ep + 7) / 8, 256>>>(ei, E, ep);
    finish_kernel<<<2048, 256>>>(bias, n);
}

extern "C" void kernel_launch(void* const* d_in, const int* in_sizes, int n_in,
                              void* d_out, int out_size) {
    const float* x     = (const float*)d_in[0];
    const int*   ei    = (const int*)d_in[1];    // int32 (JAX x64 disabled)
    const int*   batch = (const int*)d_in[2];    // int32
    const float* W1    = (const float*)d_in[3];
    const float* attS1 = (const float*)d_in[4];
    const float* attD1 = (const float*)d_in[5];
    const float* b1    = (const float*)d_in[6];
    const float* W2    = (const float*)d_in[7];
    const float* attS2 = (const float*)d_in[8];
    const float* attD2 = (const float*)d_in[9];
    const float* b2    = (const float*)d_in[10];
    const float* Wo    = (const float*)d_in[11];
    const float* bo    = (const float*)d_in[12];
    const float* Wg    = (const float*)d_in[13];
    const float* bg    = (const float*)d_in[14];
    const float* Wa    = (const float*)d_in[15];
    const float* ba    = (const float*)d_in[16];

    int n  = in_sizes[0] / 128;
    int E  = in_sizes[1] / 2;
    int ep = E + n;

    // ---- Layer 1: input x [n,128] ----
    init_layer_kernel<<<2048, 256>>>(n);
    gemm_kernel<128, false><<<(n + 63) / 64, 256>>>(x, W1, n);
    run_edge_phase(attS1, attD1, b1, ei, n, E, ep);

    // ---- Layer 2: input g_out1 [n,64] (read inside kernel) ----
    init_layer_kernel<<<2048, 256>>>(n);
    gemm_kernel<64, true><<<(n + 63) / 64, 256>>>(nullptr, W2, n);
    run_edge_phase(attS2, attD2, b2, ei, n, E, ep);

    // ---- Pooling ----
    init_pool_kernel<<<1, 256>>>();
    poolprep_kernel<<<(n + 255) / 256, 256>>>(batch, n);
    poolsum_kernel<<<GMAX, 64>>>(n);

    // ---- Heads ----
    heads_kernel<<<GMAX, 64>>>(Wo, bo, Wg, bg, Wa, ba, (float*)d_out);
}

// round 4
// speedup vs baseline: 1.8866x; 1.8866x over previous
#include <cuda_runtime.h>
#include <cuda_bf16.h>
#include <math.h>

// ---------------------------------------------------------------------------
// Problem constants
// ---------------------------------------------------------------------------
#define NMAX   100000
#define EMAX   1600000
#define EPMAX  (EMAX + NMAX)
#define GMAX   256
#define SCAN_BLK 1024
#define SCAN_NB  ((NMAX + SCAN_BLK - 1) / SCAN_BLK)   // 98

// ---------------------------------------------------------------------------
// Scratch (device globals; no allocation allowed)
// ---------------------------------------------------------------------------
__device__ __align__(16) float g_h[(size_t)NMAX * 128];   // h = A @ W  [N, 2*64]
__device__ __align__(16) float g_out1[(size_t)NMAX * 64]; // layer out  [N, 64]
__device__ __align__(16) float g_asrc[NMAX * 2];
__device__ __align__(16) float g_adst[NMAX * 2];
__device__ __align__(16) float g_pool[GMAX * 64];
__device__ float               g_cnt[GMAX];
__device__ int                 g_gstart[GMAX];
// CSR (built once, reused by both layers)
__device__ int g_deg[NMAX];
__device__ int g_scan[NMAX];
__device__ int g_bsum[128];
__device__ int g_bpre[128];
__device__ int g_off[NMAX + 1];
__device__ int g_cur[NMAX];
__device__ int g_csr_src[EPMAX];

// ---------------------------------------------------------------------------
// CSR build: degree histogram (self-loop baked in as init=1)
// ---------------------------------------------------------------------------
__global__ void deginit_kernel(int n) {
    int i = blockIdx.x * blockDim.x + threadIdx.x;
    if (i < n) g_deg[i] = 1;           // self loop
}

__global__ void hist_kernel(const int* __restrict__ ei, int E) {
    int e = blockIdx.x * blockDim.x + threadIdx.x;
    if (e < E) atomicAdd(&g_deg[ei[E + e]], 1);
}

// Block-level inclusive scan (Hillis-Steele)
__global__ void scan1_kernel(int n) {
    __shared__ int sm[SCAN_BLK];
    int i = blockIdx.x * SCAN_BLK + threadIdx.x;
    int v = (i < n) ? g_deg[i] : 0;
    sm[threadIdx.x] = v;
    __syncthreads();
#pragma unroll
    for (int o = 1; o < SCAN_BLK; o <<= 1) {
        int t = (threadIdx.x >= o) ? sm[threadIdx.x - o] : 0;
        __syncthreads();
        sm[threadIdx.x] += t;
        __syncthreads();
    }
    if (i < n) g_scan[i] = sm[threadIdx.x];
    if (threadIdx.x == SCAN_BLK - 1) g_bsum[blockIdx.x] = sm[threadIdx.x];
}

__global__ void scan2_kernel(int nb) {    // single block, 128 threads
    __shared__ int sm[128];
    int v = (threadIdx.x < nb) ? g_bsum[threadIdx.x] : 0;
    sm[threadIdx.x] = v;
    __syncthreads();
#pragma unroll
    for (int o = 1; o < 128; o <<= 1) {
        int t = (threadIdx.x >= o) ? sm[threadIdx.x - o] : 0;
        __syncthreads();
        sm[threadIdx.x] += t;
        __syncthreads();
    }
    if (threadIdx.x < nb) g_bpre[threadIdx.x] = sm[threadIdx.x] - v;  // exclusive
}

__global__ void scan3_kernel(int n) {
    int i = blockIdx.x * blockDim.x + threadIdx.x;
    if (i >= n) return;
    int incl = g_scan[i] + g_bpre[i / SCAN_BLK];
    int off  = incl - g_deg[i];
    g_off[i] = off;
    g_cur[i] = off;
    if (i == n - 1) g_off[n] = incl;
}

__global__ void fill_kernel(const int* __restrict__ ei, int E, int ep) {
    int e = blockIdx.x * blockDim.x + threadIdx.x;
    if (e >= ep) return;
    int s, d;
    if (e < E) { s = ei[e]; d = ei[E + e]; }
    else       { s = e - E; d = s; }
    int pos = atomicAdd(&g_cur[d], 1);
    g_csr_src[pos] = s;
}

// ---------------------------------------------------------------------------
// Tiled GEMM: g_h[n,128] = A[n,K] @ W[K,128]
// ---------------------------------------------------------------------------
template <int K, bool FROM_GLOBAL>
__global__ void gemm_kernel(const float* __restrict__ Ain,
                            const float* __restrict__ W, int n) {
    const float* __restrict__ A = FROM_GLOBAL ? (const float*)g_out1 : Ain;
    __shared__ __align__(16) float As[64 * 32];
    __shared__ __align__(16) float Ws[32 * 128];
    const int tid = threadIdx.x;
    const int q  = tid & 31;
    const int rg = tid >> 5;
    const int tile = blockIdx.x * 64;
    if (tile >= n) return;

    float acc[8][4];
#pragma unroll
    for (int r = 0; r < 8; r++)
#pragma unroll
        for (int c = 0; c < 4; c++) acc[r][c] = 0.0f;

    for (int kk = 0; kk < K; kk += 32) {
        __syncthreads();
#pragma unroll
        for (int i = tid; i < 64 * 32; i += 256) {
            int r = i >> 5, c = i & 31;
            int row = tile + r;
            As[i] = (row < n) ? A[(size_t)row * K + kk + c] : 0.0f;
        }
#pragma unroll
        for (int i = tid; i < 32 * 128; i += 256) {
            Ws[i] = W[(size_t)(kk + (i >> 7)) * 128 + (i & 127)];
        }
        __syncthreads();
#pragma unroll
        for (int k = 0; k < 32; k++) {
            float4 w = *(const float4*)&Ws[k * 128 + q * 4];
#pragma unroll
            for (int r = 0; r < 8; r++) {
                float a = As[(rg * 8 + r) * 32 + k];
                acc[r][0] += a * w.x;
                acc[r][1] += a * w.y;
                acc[r][2] += a * w.z;
                acc[r][3] += a * w.w;
            }
        }
    }
#pragma unroll
    for (int r = 0; r < 8; r++) {
        int row = tile + rg * 8 + r;
        if (row < n) {
            float4 v = make_float4(acc[r][0], acc[r][1], acc[r][2], acc[r][3]);
            *(float4*)&g_h[(size_t)row * 128 + q * 4] = v;
        }
    }
}

// ---------------------------------------------------------------------------
// Attention coefficients: warp per node
// ---------------------------------------------------------------------------
__global__ void att_kernel(const float* __restrict__ attS,
                           const float* __restrict__ attD, int n) {
    int w = (blockIdx.x * blockDim.x + threadIdx.x) >> 5;
    if (w >= n) return;
    int lane = threadIdx.x & 31;
    const float* hr = g_h + (size_t)w * 128;

    float s0 = hr[lane] * attS[lane] + hr[lane + 32] * attS[lane + 32];
    float d0 = hr[lane] * attD[lane] + hr[lane + 32] * attD[lane + 32];
    float s1 = hr[64 + lane] * attS[64 + lane] + hr[96 + lane] * attS[96 + lane];
    float d1 = hr[64 + lane] * attD[64 + lane] + hr[96 + lane] * attD[96 + lane];
#pragma unroll
    for (int o = 16; o; o >>= 1) {
        s0 += __shfl_down_sync(0xFFFFFFFFu, s0, o);
        s1 += __shfl_down_sync(0xFFFFFFFFu, s1, o);
        d0 += __shfl_down_sync(0xFFFFFFFFu, d0, o);
        d1 += __shfl_down_sync(0xFFFFFFFFu, d1, o);
    }
    if (lane == 0) {
        g_asrc[w * 2] = s0; g_asrc[w * 2 + 1] = s1;
        g_adst[w * 2] = d0; g_adst[w * 2 + 1] = d1;
    }
}

// ---------------------------------------------------------------------------
// Fused edge phase: warp per dst node.
// Deferred normalization: out = (Σ x0·hA)·(0.5/Σx0) + (Σ x1·hB)·(0.5/Σx1)
// Single loop over incoming edges; no atomics, no scratch, epilogue fused.
// ---------------------------------------------------------------------------
__global__ void gat_node_kernel(const float* __restrict__ bias, int n) {
    int node = (blockIdx.x * blockDim.x + threadIdx.x) >> 5;
    if (node >= n) return;
    int lane = threadIdx.x & 31;
    int beg = g_off[node], end = g_off[node + 1];
    float2 ad = *(const float2*)&g_adst[node * 2];

    float sum0 = 0.f, sum1 = 0.f;
    float a0x = 0.f, a0y = 0.f, a1x = 0.f, a1y = 0.f;
    const int f = lane * 2;

    for (int c = beg; c < end; c += 32) {
        int m = end - c;
        if (m > 32) m = 32;
        int   sj = 0;
        float x0 = 0.f, x1 = 0.f;
        if (lane < m) {
            sj = g_csr_src[c + lane];
            float2 as = *(const float2*)&g_asrc[sj * 2];
            float e0 = as.x + ad.x;
            float e1 = as.y + ad.y;
            e0 = (e0 > 0.f) ? e0 : 0.2f * e0;
            e1 = (e1 > 0.f) ? e1 : 0.2f * e1;
            x0 = __expf(e0);
            x1 = __expf(e1);
            sum0 += x0;
            sum1 += x1;
        }
        if (m == 32) {
#pragma unroll 8
            for (int k = 0; k < 32; k++) {
                int   s  = __shfl_sync(0xFFFFFFFFu, sj, k);
                float w0 = __shfl_sync(0xFFFFFFFFu, x0, k);
                float w1 = __shfl_sync(0xFFFFFFFFu, x1, k);
                const float* hp = g_h + (size_t)s * 128;
                float2 hA = *(const float2*)(hp + f);
                float2 hB = *(const float2*)(hp + 64 + f);
                a0x += w0 * hA.x; a0y += w0 * hA.y;
                a1x += w1 * hB.x; a1y += w1 * hB.y;
            }
        } else {
            for (int k = 0; k < m; k++) {
                int   s  = __shfl_sync(0xFFFFFFFFu, sj, k);
                float w0 = __shfl_sync(0xFFFFFFFFu, x0, k);
                float w1 = __shfl_sync(0xFFFFFFFFu, x1, k);
                const float* hp = g_h + (size_t)s * 128;
                float2 hA = *(const float2*)(hp + f);
                float2 hB = *(const float2*)(hp + 64 + f);
                a0x += w0 * hA.x; a0y += w0 * hA.y;
                a1x += w1 * hB.x; a1y += w1 * hB.y;
            }
        }
    }
#pragma unroll
    for (int o = 16; o; o >>= 1) {
        sum0 += __shfl_xor_sync(0xFFFFFFFFu, sum0, o);
        sum1 += __shfl_xor_sync(0xFFFFFFFFu, sum1, o);
    }
    float inv0 = 0.5f / sum0;
    float inv1 = 0.5f / sum1;
    float vx = a0x * inv0 + a1x * inv1 + bias[f];
    float vy = a0y * inv0 + a1y * inv1 + bias[f + 1];
    vx = (vx > 0.f) ? vx : 0.f;
    vy = (vy > 0.f) ? vy : 0.f;
    *(float2*)&g_out1[(size_t)node * 64 + f] = make_float2(vx, vy);
}

// ---------------------------------------------------------------------------
// Pooling (batch sorted -> contiguous ranges)
// ---------------------------------------------------------------------------
__global__ void init_pool_kernel() {
    int t = threadIdx.x;
    if (t < GMAX) { g_cnt[t] = 0.0f; g_gstart[t] = 0x7FFFFFFF; }
}

__global__ void poolprep_kernel(const int* __restrict__ batch, int n) {
    int i = blockIdx.x * blockDim.x + threadIdx.x;
    if (i >= n) return;
    int b = batch[i];
    atomicAdd(&g_cnt[b], 1.0f);
    atomicMin(&g_gstart[b], i);
}

__global__ void poolsum_kernel(int n) {
    int g = blockIdx.x;
    int t = threadIdx.x;
    float c   = g_cnt[g];
    int   cnt = (int)c;
    float a0 = 0.f, a1 = 0.f, a2 = 0.f, a3 = 0.f;
    if (cnt > 0) {
        int st = g_gstart[g];
        int i = 0;
        for (; i + 4 <= cnt; i += 4) {
            a0 += g_out1[(size_t)(st + i)     * 64 + t];
            a1 += g_out1[(size_t)(st + i + 1) * 64 + t];
            a2 += g_out1[(size_t)(st + i + 2) * 64 + t];
            a3 += g_out1[(size_t)(st + i + 3) * 64 + t];
        }
        for (; i < cnt; i++) a0 += g_out1[(size_t)(st + i) * 64 + t];
    }
    g_pool[g * 64 + t] = (a0 + a1 + a2 + a3) / fmaxf(c, 1.0f);
}

// ---------------------------------------------------------------------------
// Heads
// ---------------------------------------------------------------------------
__device__ void softmax_out(const float* l, int sz, float* o) {
    float m = -1e30f;
    for (int i = 0; i < sz; i++) m = fmaxf(m, l[i]);
    float s = 0.0f;
    for (int i = 0; i < sz; i++) s += expf(l[i] - m);
    float inv = 1.0f / s;
    for (int i = 0; i < sz; i++) o[i] = expf(l[i] - m) * inv;
}

__global__ void heads_kernel(const float* __restrict__ Wo, const float* __restrict__ bo,
                             const float* __restrict__ Wg, const float* __restrict__ bg,
                             const float* __restrict__ Wa, const float* __restrict__ ba,
                             float* __restrict__ out) {
    __shared__ float p[64];
    __shared__ float l[56];
    int g = blockIdx.x;
    int t = threadIdx.x;
    p[t] = g_pool[g * 64 + t];
    __syncthreads();
    if (t < 32) {
        float acc = bo[t];
        for (int k = 0; k < 64; k++) acc += p[k] * Wo[k * 32 + t];
        l[t] = acc;
    } else if (t < 48) {
        int j = t - 32;
        float acc = bg[j];
        for (int k = 0; k < 64; k++) acc += p[k] * Wg[k * 16 + j];
        l[32 + j] = acc;
    } else if (t < 56) {
        int j = t - 48;
        float acc = ba[j];
        for (int k = 0; k < 64; k++) acc += p[k] * Wa[k * 8 + j];
        l[48 + j] = acc;
    }
    __syncthreads();
    if (t == 0) softmax_out(l,      32, out + g * 32);
    if (t == 1) softmax_out(l + 32, 16, out + 8192  + g * 16);
    if (t == 2) softmax_out(l + 48, 8,  out + 12288 + g * 8);
}

// ---------------------------------------------------------------------------
// Host driver
// ---------------------------------------------------------------------------
extern "C" void kernel_launch(void* const* d_in, const int* in_sizes, int n_in,
                              void* d_out, int out_size) {
    const float* x     = (const float*)d_in[0];
    const int*   ei    = (const int*)d_in[1];
    const int*   batch = (const int*)d_in[2];
    const float* W1    = (const float*)d_in[3];
    const float* attS1 = (const float*)d_in[4];
    const float* attD1 = (const float*)d_in[5];
    const float* b1    = (const float*)d_in[6];
    const float* W2    = (const float*)d_in[7];
    const float* attS2 = (const float*)d_in[8];
    const float* attD2 = (const float*)d_in[9];
    const float* b2    = (const float*)d_in[10];
    const float* Wo    = (const float*)d_in[11];
    const float* bo    = (const float*)d_in[12];
    const float* Wg    = (const float*)d_in[13];
    const float* bg    = (const float*)d_in[14];
    const float* Wa    = (const float*)d_in[15];
    const float* ba    = (const float*)d_in[16];

    int n  = in_sizes[0] / 128;
    int E  = in_sizes[1] / 2;
    int ep = E + n;
    int nb = (n + SCAN_BLK - 1) / SCAN_BLK;

    // ---- CSR build (once; reused by both layers) ----
    deginit_kernel<<<(n + 255) / 256, 256>>>(n);
    hist_kernel<<<(E + 255) / 256, 256>>>(ei, E);
    scan1_kernel<<<nb, SCAN_BLK>>>(n);
    scan2_kernel<<<1, 128>>>(nb);
    scan3_kernel<<<(n + 255) / 256, 256>>>(n);
    fill_kernel<<<(ep + 255) / 256, 256>>>(ei, E, ep);

    // ---- Layer 1 ----
    gemm_kernel<128, false><<<(n + 63) / 64, 256>>>(x, W1, n);
    att_kernel<<<((size_t)n * 32 + 255) / 256, 256>>>(attS1, attD1, n);
    gat_node_kernel<<<((size_t)n * 32 + 255) / 256, 256>>>(b1, n);

    // ---- Layer 2 ----
    gemm_kernel<64, true><<<(n + 63) / 64, 256>>>(nullptr, W2, n);
    att_kernel<<<((size_t)n * 32 + 255) / 256, 256>>>(attS2, attD2, n);
    gat_node_kernel<<<((size_t)n * 32 + 255) / 256, 256>>>(b2, n);

    // ---- Pooling ----
    init_pool_kernel<<<1, 256>>>();
    poolprep_kernel<<<(n + 255) / 256, 256>>>(batch, n);
    poolsum_kernel<<<GMAX, 64>>>(n);

    // ---- Heads ----
    heads_kernel<<<GMAX, 64>>>(Wo, bo, Wg, bg, Wa, ba, (float*)d_out);
}

// round 6
// speedup vs baseline: 2.0154x; 1.0682x over previous
#include <cuda_runtime.h>
#include <cuda_fp16.h>
#include <math.h>

// ---------------------------------------------------------------------------
// Problem constants
// ---------------------------------------------------------------------------
#define NMAX   100000
#define EMAX   1600000
#define EPMAX  (EMAX + NMAX)
#define GMAX   256
#define SCAN_BLK 1024

// ---------------------------------------------------------------------------
// Scratch (device globals; no allocation allowed)
// ---------------------------------------------------------------------------
__device__ __align__(16) __half g_hh[(size_t)NMAX * 128];  // h (fp16) [N,128]
__device__ __align__(16) float  g_out1[(size_t)NMAX * 64]; // layer out [N,64]
__device__ __align__(16) float  g_asrc[NMAX * 2];
__device__ __align__(16) float  g_adst[NMAX * 2];
__device__ __align__(16) float  g_pool[GMAX * 64];
__device__ float                g_cnt[GMAX];
__device__ int                  g_gstart[GMAX];
// CSR (built once, reused by both layers)
__device__ int g_deg[NMAX];
__device__ int g_scan[NMAX];
__device__ int g_bsum[128];
__device__ int g_bpre[128];
__device__ int g_off[NMAX + 1];
__device__ int g_cur[NMAX];
__device__ int g_csr_src[EPMAX];

// ---------------------------------------------------------------------------
// CSR build
// ---------------------------------------------------------------------------
__global__ void deginit_kernel(int n) {
    int i = blockIdx.x * blockDim.x + threadIdx.x;
    if (i < n) g_deg[i] = 1;           // self loop
}

__global__ void hist_kernel(const int* __restrict__ ei, int E) {
    int e = blockIdx.x * blockDim.x + threadIdx.x;
    if (e < E) atomicAdd(&g_deg[ei[E + e]], 1);
}

__global__ void scan1_kernel(int n) {
    __shared__ int sm[SCAN_BLK];
    int i = blockIdx.x * SCAN_BLK + threadIdx.x;
    int v = (i < n) ? g_deg[i] : 0;
    sm[threadIdx.x] = v;
    __syncthreads();
#pragma unroll
    for (int o = 1; o < SCAN_BLK; o <<= 1) {
        int t = (threadIdx.x >= o) ? sm[threadIdx.x - o] : 0;
        __syncthreads();
        sm[threadIdx.x] += t;
        __syncthreads();
    }
    if (i < n) g_scan[i] = sm[threadIdx.x];
    if (threadIdx.x == SCAN_BLK - 1) g_bsum[blockIdx.x] = sm[threadIdx.x];
}

__global__ void scan2_kernel(int nb) {
    __shared__ int sm[128];
    int v = (threadIdx.x < nb) ? g_bsum[threadIdx.x] : 0;
    sm[threadIdx.x] = v;
    __syncthreads();
#pragma unroll
    for (int o = 1; o < 128; o <<= 1) {
        int t = (threadIdx.x >= o) ? sm[threadIdx.x - o] : 0;
        __syncthreads();
        sm[threadIdx.x] += t;
        __syncthreads();
    }
    if (threadIdx.x < nb) g_bpre[threadIdx.x] = sm[threadIdx.x] - v;
}

__global__ void scan3_kernel(int n) {
    int i = blockIdx.x * blockDim.x + threadIdx.x;
    if (i >= n) return;
    int incl = g_scan[i] + g_bpre[i / SCAN_BLK];
    int off  = incl - g_deg[i];
    g_off[i] = off;
    g_cur[i] = off;
    if (i == n - 1) g_off[n] = incl;
}

__global__ void fill_kernel(const int* __restrict__ ei, int E, int ep) {
    int e = blockIdx.x * blockDim.x + threadIdx.x;
    if (e >= ep) return;
    int s, d;
    if (e < E) { s = ei[e]; d = ei[E + e]; }
    else       { s = e - E; d = s; }
    int pos = atomicAdd(&g_cur[d], 1);
    g_csr_src[pos] = s;
}

// ---------------------------------------------------------------------------
// Tiled GEMM + fused attention-coefficient epilogue.
// Writes h as fp16 to g_hh and a_src/a_dst (fp32) to g_asrc/g_adst.
// Warp layout: warp rg owns rows tile+rg*8 .. +7, lane q owns cols 4q..4q+3,
// so each warp holds complete rows -> per-row att dot via 16-lane reduction.
// ---------------------------------------------------------------------------
template <int K, bool FROM_GLOBAL>
__global__ void gemm_kernel(const float* __restrict__ Ain,
                            const float* __restrict__ W,
                            const float* __restrict__ attS,
                            const float* __restrict__ attD, int n) {
    const float* __restrict__ A = FROM_GLOBAL ? (const float*)g_out1 : Ain;
    __shared__ __align__(16) float As[64 * 32];
    __shared__ __align__(16) float Ws[32 * 128];
    const int tid = threadIdx.x;
    const int q  = tid & 31;
    const int rg = tid >> 5;
    const int tile = blockIdx.x * 64;
    if (tile >= n) return;

    float acc[8][4];
#pragma unroll
    for (int r = 0; r < 8; r++)
#pragma unroll
        for (int c = 0; c < 4; c++) acc[r][c] = 0.0f;

    for (int kk = 0; kk < K; kk += 32) {
        __syncthreads();
#pragma unroll
        for (int i = tid; i < 64 * 32; i += 256) {
            int r = i >> 5, c = i & 31;
            int row = tile + r;
            As[i] = (row < n) ? A[(size_t)row * K + kk + c] : 0.0f;
        }
#pragma unroll
        for (int i = tid; i < 32 * 128; i += 256) {
            Ws[i] = W[(size_t)(kk + (i >> 7)) * 128 + (i & 127)];
        }
        __syncthreads();
#pragma unroll
        for (int k = 0; k < 32; k++) {
            float4 w = *(const float4*)&Ws[k * 128 + q * 4];
#pragma unroll
            for (int r = 0; r < 8; r++) {
                float a = As[(rg * 8 + r) * 32 + k];
                acc[r][0] += a * w.x;
                acc[r][1] += a * w.y;
                acc[r][2] += a * w.z;
                acc[r][3] += a * w.w;
            }
        }
    }

    // att vectors for this lane's 4 columns (att[HEADS,HID] flattened = [128])
    float4 vS = *(const float4*)&attS[q * 4];
    float4 vD = *(const float4*)&attD[q * 4];

#pragma unroll
    for (int r = 0; r < 8; r++) {
        int row = tile + rg * 8 + r;
        if (row >= n) continue;
        // fp16 h store (coalesced 8B per lane)
        __half2 p0 = __floats2half2_rn(acc[r][0], acc[r][1]);
        __half2 p1 = __floats2half2_rn(acc[r][2], acc[r][3]);
        __half2* hp = (__half2*)(g_hh + (size_t)row * 128);
        hp[q * 2]     = p0;
        hp[q * 2 + 1] = p1;
        // fused att dot: reduce within each 16-lane half (head0: q<16, head1: q>=16)
        float ps = acc[r][0] * vS.x + acc[r][1] * vS.y + acc[r][2] * vS.z + acc[r][3] * vS.w;
        float pd = acc[r][0] * vD.x + acc[r][1] * vD.y + acc[r][2] * vD.z + acc[r][3] * vD.w;
#pragma unroll
        for (int o = 8; o; o >>= 1) {
            ps += __shfl_xor_sync(0xFFFFFFFFu, ps, o);
            pd += __shfl_xor_sync(0xFFFFFFFFu, pd, o);
        }
        // lane 0 has head0 sum, lane 16 has head1 sum
        float ps1 = __shfl_sync(0xFFFFFFFFu, ps, 16);
        float pd1 = __shfl_sync(0xFFFFFFFFu, pd, 16);
        if (q == 0) {
            *(float2*)&g_asrc[row * 2] = make_float2(ps, ps1);
            *(float2*)&g_adst[row * 2] = make_float2(pd, pd1);
        }
    }
}

// ---------------------------------------------------------------------------
// Fused edge phase: warp per dst node, fp16 h gathers.
// out = (Σ x0·hA)·(0.5/Σx0) + (Σ x1·hB)·(0.5/Σx1)   (deferred normalization)
// ---------------------------------------------------------------------------
__global__ void gat_node_kernel(const float* __restrict__ bias, int n) {
    int node = (blockIdx.x * blockDim.x + threadIdx.x) >> 5;
    if (node >= n) return;
    int lane = threadIdx.x & 31;
    int beg = g_off[node], end = g_off[node + 1];
    float2 ad = *(const float2*)&g_adst[node * 2];

    float sum0 = 0.f, sum1 = 0.f;
    float a0x = 0.f, a0y = 0.f, a1x = 0.f, a1y = 0.f;
    const int f = lane * 2;

    for (int c = beg; c < end; c += 32) {
        int m = end - c;
        if (m > 32) m = 32;
        int   sj = 0;
        float x0 = 0.f, x1 = 0.f;
        if (lane < m) {
            sj = g_csr_src[c + lane];
            float2 as = *(const float2*)&g_asrc[sj * 2];
            float e0 = as.x + ad.x;
            float e1 = as.y + ad.y;
            e0 = (e0 > 0.f) ? e0 : 0.2f * e0;
            e1 = (e1 > 0.f) ? e1 : 0.2f * e1;
            x0 = __expf(e0);
            x1 = __expf(e1);
            sum0 += x0;
            sum1 += x1;
        }
        if (m == 32) {
#pragma unroll 8
            for (int k = 0; k < 32; k++) {
                int   s  = __shfl_sync(0xFFFFFFFFu, sj, k);
                float w0 = __shfl_sync(0xFFFFFFFFu, x0, k);
                float w1 = __shfl_sync(0xFFFFFFFFu, x1, k);
                const __half2* hp = (const __half2*)(g_hh + (size_t)s * 128);
                float2 hA = __half22float2(hp[lane]);
                float2 hB = __half22float2(hp[32 + lane]);
                a0x += w0 * hA.x; a0y += w0 * hA.y;
                a1x += w1 * hB.x; a1y += w1 * hB.y;
            }
        } else {
            for (int k = 0; k < m; k++) {
                int   s  = __shfl_sync(0xFFFFFFFFu, sj, k);
                float w0 = __shfl_sync(0xFFFFFFFFu, x0, k);
                float w1 = __shfl_sync(0xFFFFFFFFu, x1, k);
                const __half2* hp = (const __half2*)(g_hh + (size_t)s * 128);
                float2 hA = __half22float2(hp[lane]);
                float2 hB = __half22float2(hp[32 + lane]);
                a0x += w0 * hA.x; a0y += w0 * hA.y;
                a1x += w1 * hB.x; a1y += w1 * hB.y;
            }
        }
    }
#pragma unroll
    for (int o = 16; o; o >>= 1) {
        sum0 += __shfl_xor_sync(0xFFFFFFFFu, sum0, o);
        sum1 += __shfl_xor_sync(0xFFFFFFFFu, sum1, o);
    }
    float inv0 = 0.5f / sum0;
    float inv1 = 0.5f / sum1;
    float vx = a0x * inv0 + a1x * inv1 + bias[f];
    float vy = a0y * inv0 + a1y * inv1 + bias[f + 1];
    vx = (vx > 0.f) ? vx : 0.f;
    vy = (vy > 0.f) ? vy : 0.f;
    *(float2*)&g_out1[(size_t)node * 64 + f] = make_float2(vx, vy);
}

// ---------------------------------------------------------------------------
// Pooling (batch sorted -> contiguous ranges)
// ---------------------------------------------------------------------------
__global__ void init_pool_kernel() {
    int t = threadIdx.x;
    if (t < GMAX) { g_cnt[t] = 0.0f; g_gstart[t] = 0x7FFFFFFF; }
}

__global__ void poolprep_kernel(const int* __restrict__ batch, int n) {
    int i = blockIdx.x * blockDim.x + threadIdx.x;
    if (i >= n) return;
    int b = batch[i];
    atomicAdd(&g_cnt[b], 1.0f);
    atomicMin(&g_gstart[b], i);
}

__global__ void poolsum_kernel(int n) {
    int g = blockIdx.x;
    int t = threadIdx.x;
    float c   = g_cnt[g];
    int   cnt = (int)c;
    float a0 = 0.f, a1 = 0.f, a2 = 0.f, a3 = 0.f;
    if (cnt > 0) {
        int st = g_gstart[g];
        int i = 0;
        for (; i + 4 <= cnt; i += 4) {
            a0 += g_out1[(size_t)(st + i)     * 64 + t];
            a1 += g_out1[(size_t)(st + i + 1) * 64 + t];
            a2 += g_out1[(size_t)(st + i + 2) * 64 + t];
            a3 += g_out1[(size_t)(st + i + 3) * 64 + t];
        }
        for (; i < cnt; i++) a0 += g_out1[(size_t)(st + i) * 64 + t];
    }
    g_pool[g * 64 + t] = (a0 + a1 + a2 + a3) / fmaxf(c, 1.0f);
}

// ---------------------------------------------------------------------------
// Heads
// ---------------------------------------------------------------------------
__device__ void softmax_out(const float* l, int sz, float* o) {
    float m = -1e30f;
    for (int i = 0; i < sz; i++) m = fmaxf(m, l[i]);
    float s = 0.0f;
    for (int i = 0; i < sz; i++) s += expf(l[i] - m);
    float inv = 1.0f / s;
    for (int i = 0; i < sz; i++) o[i] = expf(l[i] - m) * inv;
}

__global__ void heads_kernel(const float* __restrict__ Wo, const float* __restrict__ bo,
                             const float* __restrict__ Wg, const float* __restrict__ bg,
                             const float* __restrict__ Wa, const float* __restrict__ ba,
                             float* __restrict__ out) {
    __shared__ float p[64];
    __shared__ float l[56];
    int g = blockIdx.x;
    int t = threadIdx.x;
    p[t] = g_pool[g * 64 + t];
    __syncthreads();
    if (t < 32) {
        float acc = bo[t];
        for (int k = 0; k < 64; k++) acc += p[k] * Wo[k * 32 + t];
        l[t] = acc;
    } else if (t < 48) {
        int j = t - 32;
        float acc = bg[j];
        for (int k = 0; k < 64; k++) acc += p[k] * Wg[k * 16 + j];
        l[32 + j] = acc;
    } else if (t < 56) {
        int j = t - 48;
        float acc = ba[j];
        for (int k = 0; k < 64; k++) acc += p[k] * Wa[k * 8 + j];
        l[48 + j] = acc;
    }
    __syncthreads();
    if (t == 0) softmax_out(l,      32, out + g * 32);
    if (t == 1) softmax_out(l + 32, 16, out + 8192  + g * 16);
    if (t == 2) softmax_out(l + 48, 8,  out + 12288 + g * 8);
}

// ---------------------------------------------------------------------------
// Host driver
// ---------------------------------------------------------------------------
extern "C" void kernel_launch(void* const* d_in, const int* in_sizes, int n_in,
                              void* d_out, int out_size) {
    const float* x     = (const float*)d_in[0];
    const int*   ei    = (const int*)d_in[1];
    const int*   batch = (const int*)d_in[2];
    const float* W1    = (const float*)d_in[3];
    const float* attS1 = (const float*)d_in[4];
    const float* attD1 = (const float*)d_in[5];
    const float* b1    = (const float*)d_in[6];
    const float* W2    = (const float*)d_in[7];
    const float* attS2 = (const float*)d_in[8];
    const float* attD2 = (const float*)d_in[9];
    const float* b2    = (const float*)d_in[10];
    const float* Wo    = (const float*)d_in[11];
    const float* bo    = (const float*)d_in[12];
    const float* Wg    = (const float*)d_in[13];
    const float* bg    = (const float*)d_in[14];
    const float* Wa    = (const float*)d_in[15];
    const float* ba    = (const float*)d_in[16];

    int n  = in_sizes[0] / 128;
    int E  = in_sizes[1] / 2;
    int ep = E + n;
    int nb = (n + SCAN_BLK - 1) / SCAN_BLK;

    // ---- CSR build (once; reused by both layers) ----
    deginit_kernel<<<(n + 255) / 256, 256>>>(n);
    hist_kernel<<<(E + 255) / 256, 256>>>(ei, E);
    scan1_kernel<<<nb, SCAN_BLK>>>(n);
    scan2_kernel<<<1, 128>>>(nb);
    scan3_kernel<<<(n + 255) / 256, 256>>>(n);
    fill_kernel<<<(ep + 255) / 256, 256>>>(ei, E, ep);

    // ---- Layer 1 (GEMM writes fp16 h + att coefficients) ----
    gemm_kernel<128, false><<<(n + 63) / 64, 256>>>(x, W1, attS1, attD1, n);
    gat_node_kernel<<<((size_t)n * 32 + 255) / 256, 256>>>(b1, n);

    // ---- Layer 2 ----
    gemm_kernel<64, true><<<(n + 63) / 64, 256>>>(nullptr, W2, attS2, attD2, n);
    gat_node_kernel<<<((size_t)n * 32 + 255) / 256, 256>>>(b2, n);

    // ---- Pooling ----
    init_pool_kernel<<<1, 256>>>();
    poolprep_kernel<<<(n + 255) / 256, 256>>>(batch, n);
    poolsum_kernel<<<GMAX, 64>>>(n);

    // ---- Heads ----
    heads_kernel<<<GMAX, 64>>>(Wo, bo, Wg, bg, Wa, ba, (float*)d_out);
}

// round 7
// speedup vs baseline: 2.1429x; 1.0633x over previous
#include <cuda_runtime.h>
#include <cuda_fp16.h>
#include <math.h>

// ---------------------------------------------------------------------------
// Problem constants
// ---------------------------------------------------------------------------
#define NMAX   100000
#define EMAX   1600000
#define EPMAX  (EMAX + NMAX)
#define GMAX   256
#define SCAN_BLK 1024

// ---------------------------------------------------------------------------
// Scratch (device globals; no allocation allowed)
// ---------------------------------------------------------------------------
__device__ __align__(16) __half g_hh[(size_t)NMAX * 128];  // h (fp16) [N,128]
__device__ __align__(16) float  g_out1[(size_t)NMAX * 64]; // layer out [N,64]
__device__ __align__(16) float  g_asrc[NMAX * 2];
__device__ __align__(16) float  g_adst[NMAX * 2];
__device__ __align__(16) float  g_pool[GMAX * 64];
// CSR (built once, reused by both layers)
__device__ int g_deg[NMAX];
__device__ int g_scan[NMAX];
__device__ int g_bsum[128];
__device__ int g_off[NMAX + 1];
__device__ int g_cur[NMAX];
__device__ int g_csr_src[EPMAX];

// ---------------------------------------------------------------------------
// CSR build
// ---------------------------------------------------------------------------
__global__ void deginit_kernel(int n) {
    int i = blockIdx.x * blockDim.x + threadIdx.x;
    if (i < n) g_deg[i] = 1;           // self loop
}

__global__ void hist_kernel(const int* __restrict__ ei, int E) {
    int e = blockIdx.x * blockDim.x + threadIdx.x;
    if (e < E) atomicAdd(&g_deg[ei[E + e]], 1);
}

__global__ void scan1_kernel(int n) {
    __shared__ int sm[SCAN_BLK];
    int i = blockIdx.x * SCAN_BLK + threadIdx.x;
    int v = (i < n) ? g_deg[i] : 0;
    sm[threadIdx.x] = v;
    __syncthreads();
#pragma unroll
    for (int o = 1; o < SCAN_BLK; o <<= 1) {
        int t = (threadIdx.x >= o) ? sm[threadIdx.x - o] : 0;
        __syncthreads();
        sm[threadIdx.x] += t;
        __syncthreads();
    }
    if (i < n) g_scan[i] = sm[threadIdx.x];
    if (threadIdx.x == SCAN_BLK - 1) g_bsum[blockIdx.x] = sm[threadIdx.x];
}

// scan3 absorbs the old scan2: each thread sums the block partials before its
// own block (<=98 ints, L1-broadcast) — removes one tiny kernel launch.
__global__ void scan3_kernel(int n) {
    int i = blockIdx.x * blockDim.x + threadIdx.x;
    if (i >= n) return;
    int nb = i / SCAN_BLK;
    int pre = 0;
    for (int b = 0; b < nb; b++) pre += g_bsum[b];
    int incl = g_scan[i] + pre;
    int off  = incl - g_deg[i];
    g_off[i] = off;
    g_cur[i] = off;
    if (i == n - 1) g_off[n] = incl;
}

__global__ void fill_kernel(const int* __restrict__ ei, int E, int ep) {
    int e = blockIdx.x * blockDim.x + threadIdx.x;
    if (e >= ep) return;
    int s, d;
    if (e < E) { s = ei[e]; d = ei[E + e]; }
    else       { s = e - E; d = s; }
    int pos = atomicAdd(&g_cur[d], 1);
    g_csr_src[pos] = s;
}

// ---------------------------------------------------------------------------
// Tiled GEMM + fused attention-coefficient epilogue.
// Writes h as fp16 to g_hh and a_src/a_dst (fp32) to g_asrc/g_adst.
// ---------------------------------------------------------------------------
template <int K, bool FROM_GLOBAL>
__global__ void gemm_kernel(const float* __restrict__ Ain,
                            const float* __restrict__ W,
                            const float* __restrict__ attS,
                            const float* __restrict__ attD, int n) {
    const float* __restrict__ A = FROM_GLOBAL ? (const float*)g_out1 : Ain;
    __shared__ __align__(16) float As[64 * 32];
    __shared__ __align__(16) float Ws[32 * 128];
    const int tid = threadIdx.x;
    const int q  = tid & 31;
    const int rg = tid >> 5;
    const int tile = blockIdx.x * 64;
    if (tile >= n) return;

    float acc[8][4];
#pragma unroll
    for (int r = 0; r < 8; r++)
#pragma unroll
        for (int c = 0; c < 4; c++) acc[r][c] = 0.0f;

    for (int kk = 0; kk < K; kk += 32) {
        __syncthreads();
#pragma unroll
        for (int i = tid; i < 64 * 32; i += 256) {
            int r = i >> 5, c = i & 31;
            int row = tile + r;
            As[i] = (row < n) ? A[(size_t)row * K + kk + c] : 0.0f;
        }
#pragma unroll
        for (int i = tid; i < 32 * 128; i += 256) {
            Ws[i] = W[(size_t)(kk + (i >> 7)) * 128 + (i & 127)];
        }
        __syncthreads();
#pragma unroll
        for (int k = 0; k < 32; k++) {
            float4 w = *(const float4*)&Ws[k * 128 + q * 4];
#pragma unroll
            for (int r = 0; r < 8; r++) {
                float a = As[(rg * 8 + r) * 32 + k];
                acc[r][0] += a * w.x;
                acc[r][1] += a * w.y;
                acc[r][2] += a * w.z;
                acc[r][3] += a * w.w;
            }
        }
    }

    float4 vS = *(const float4*)&attS[q * 4];
    float4 vD = *(const float4*)&attD[q * 4];

#pragma unroll
    for (int r = 0; r < 8; r++) {
        int row = tile + rg * 8 + r;
        if (row >= n) continue;
        __half2 p0 = __floats2half2_rn(acc[r][0], acc[r][1]);
        __half2 p1 = __floats2half2_rn(acc[r][2], acc[r][3]);
        __half2* hp = (__half2*)(g_hh + (size_t)row * 128);
        hp[q * 2]     = p0;
        hp[q * 2 + 1] = p1;
        float ps = acc[r][0] * vS.x + acc[r][1] * vS.y + acc[r][2] * vS.z + acc[r][3] * vS.w;
        float pd = acc[r][0] * vD.x + acc[r][1] * vD.y + acc[r][2] * vD.z + acc[r][3] * vD.w;
#pragma unroll
        for (int o = 8; o; o >>= 1) {
            ps += __shfl_xor_sync(0xFFFFFFFFu, ps, o);
            pd += __shfl_xor_sync(0xFFFFFFFFu, pd, o);
        }
        float ps1 = __shfl_sync(0xFFFFFFFFu, ps, 16);
        float pd1 = __shfl_sync(0xFFFFFFFFu, pd, 16);
        if (q == 0) {
            *(float2*)&g_asrc[row * 2] = make_float2(ps, ps1);
            *(float2*)&g_adst[row * 2] = make_float2(pd, pd1);
        }
    }
}

// ---------------------------------------------------------------------------
// Fused edge phase: warp per dst node, fp16 h gathers, deferred normalization.
// Partial chunks (the dominant path: avg degree ~17) are unrolled x4 for MLP.
// ---------------------------------------------------------------------------
#define GAT_PROC(kk)                                                      \
    {                                                                     \
        int   s_  = __shfl_sync(0xFFFFFFFFu, sj, (kk));                   \
        float w0_ = __shfl_sync(0xFFFFFFFFu, x0, (kk));                   \
        float w1_ = __shfl_sync(0xFFFFFFFFu, x1, (kk));                   \
        const __half2* hp_ = (const __half2*)(g_hh + (size_t)s_ * 128);   \
        float2 hA_ = __half22float2(hp_[lane]);                           \
        float2 hB_ = __half22float2(hp_[32 + lane]);                      \
        a0x += w0_ * hA_.x; a0y += w0_ * hA_.y;                           \
        a1x += w1_ * hB_.x; a1y += w1_ * hB_.y;                           \
    }

__global__ void gat_node_kernel(const float* __restrict__ bias, int n) {
    int node = (blockIdx.x * blockDim.x + threadIdx.x) >> 5;
    if (node >= n) return;
    int lane = threadIdx.x & 31;
    int beg = g_off[node], end = g_off[node + 1];
    float2 ad = *(const float2*)&g_adst[node * 2];

    float sum0 = 0.f, sum1 = 0.f;
    float a0x = 0.f, a0y = 0.f, a1x = 0.f, a1y = 0.f;
    const int f = lane * 2;

    for (int c = beg; c < end; c += 32) {
        int m = end - c;
        if (m > 32) m = 32;
        int   sj = 0;
        float x0 = 0.f, x1 = 0.f;
        if (lane < m) {
            sj = g_csr_src[c + lane];
            float2 as = *(const float2*)&g_asrc[sj * 2];
            float e0 = as.x + ad.x;
            float e1 = as.y + ad.y;
            e0 = (e0 > 0.f) ? e0 : 0.2f * e0;
            e1 = (e1 > 0.f) ? e1 : 0.2f * e1;
            x0 = __expf(e0);
            x1 = __expf(e1);
            sum0 += x0;
            sum1 += x1;
        }
        if (m == 32) {
#pragma unroll
            for (int k = 0; k < 32; k += 4) {
                GAT_PROC(k); GAT_PROC(k + 1); GAT_PROC(k + 2); GAT_PROC(k + 3);
            }
        } else {
            int k = 0;
            for (; k + 4 <= m; k += 4) {
                GAT_PROC(k); GAT_PROC(k + 1); GAT_PROC(k + 2); GAT_PROC(k + 3);
            }
            for (; k < m; k++) GAT_PROC(k);
        }
    }
#pragma unroll
    for (int o = 16; o; o >>= 1) {
        sum0 += __shfl_xor_sync(0xFFFFFFFFu, sum0, o);
        sum1 += __shfl_xor_sync(0xFFFFFFFFu, sum1, o);
    }
    float inv0 = 0.5f / sum0;
    float inv1 = 0.5f / sum1;
    float vx = a0x * inv0 + a1x * inv1 + bias[f];
    float vy = a0y * inv0 + a1y * inv1 + bias[f + 1];
    vx = (vx > 0.f) ? vx : 0.f;
    vy = (vy > 0.f) ? vy : 0.f;
    *(float2*)&g_out1[(size_t)node * 64 + f] = make_float2(vx, vy);
}

// ---------------------------------------------------------------------------
// Pooling: batch sorted -> boundaries by binary search (no prep kernels)
// ---------------------------------------------------------------------------
__global__ void poolsum_kernel(const int* __restrict__ batch, int n) {
    int g = blockIdx.x;      // 256 blocks
    int t = threadIdx.x;     // 64 threads (feature)
    __shared__ int s_lo, s_hi;
    if (t == 0) {
        int lo = 0, hi = n;
        while (lo < hi) { int mid = (lo + hi) >> 1; if (batch[mid] < g) lo = mid + 1; else hi = mid; }
        s_lo = lo;
        int lo2 = lo, hi2 = n;
        while (lo2 < hi2) { int mid = (lo2 + hi2) >> 1; if (batch[mid] < g + 1) lo2 = mid + 1; else hi2 = mid; }
        s_hi = lo2;
    }
    __syncthreads();
    int st  = s_lo;
    int cnt = s_hi - s_lo;
    float a0 = 0.f, a1 = 0.f, a2 = 0.f, a3 = 0.f;
    int i = 0;
    for (; i + 4 <= cnt; i += 4) {
        a0 += g_out1[(size_t)(st + i)     * 64 + t];
        a1 += g_out1[(size_t)(st + i + 1) * 64 + t];
        a2 += g_out1[(size_t)(st + i + 2) * 64 + t];
        a3 += g_out1[(size_t)(st + i + 3) * 64 + t];
    }
    for (; i < cnt; i++) a0 += g_out1[(size_t)(st + i) * 64 + t];
    float denom = (cnt > 0) ? (float)cnt : 1.0f;
    g_pool[g * 64 + t] = (a0 + a1 + a2 + a3) / denom;
}

// ---------------------------------------------------------------------------
// Heads
// ---------------------------------------------------------------------------
__device__ void softmax_out(const float* l, int sz, float* o) {
    float m = -1e30f;
    for (int i = 0; i < sz; i++) m = fmaxf(m, l[i]);
    float s = 0.0f;
    for (int i = 0; i < sz; i++) s += expf(l[i] - m);
    float inv = 1.0f / s;
    for (int i = 0; i < sz; i++) o[i] = expf(l[i] - m) * inv;
}

__global__ void heads_kernel(const float* __restrict__ Wo, const float* __restrict__ bo,
                             const float* __restrict__ Wg, const float* __restrict__ bg,
                             const float* __restrict__ Wa, const float* __restrict__ ba,
                             float* __restrict__ out) {
    __shared__ float p[64];
    __shared__ float l[56];
    int g = blockIdx.x;
    int t = threadIdx.x;
    p[t] = g_pool[g * 64 + t];
    __syncthreads();
    if (t < 32) {
        float acc = bo[t];
        for (int k = 0; k < 64; k++) acc += p[k] * Wo[k * 32 + t];
        l[t] = acc;
    } else if (t < 48) {
        int j = t - 32;
        float acc = bg[j];
        for (int k = 0; k < 64; k++) acc += p[k] * Wg[k * 16 + j];
        l[32 + j] = acc;
    } else if (t < 56) {
        int j = t - 48;
        float acc = ba[j];
        for (int k = 0; k < 64; k++) acc += p[k] * Wa[k * 8 + j];
        l[48 + j] = acc;
    }
    __syncthreads();
    if (t == 0) softmax_out(l,      32, out + g * 32);
    if (t == 1) softmax_out(l + 32, 16, out + 8192  + g * 16);
    if (t == 2) softmax_out(l + 48, 8,  out + 12288 + g * 8);
}

// ---------------------------------------------------------------------------
// Host driver
// ---------------------------------------------------------------------------
extern "C" void kernel_launch(void* const* d_in, const int* in_sizes, int n_in,
                              void* d_out, int out_size) {
    const float* x     = (const float*)d_in[0];
    const int*   ei    = (const int*)d_in[1];
    const int*   batch = (const int*)d_in[2];
    const float* W1    = (const float*)d_in[3];
    const float* attS1 = (const float*)d_in[4];
    const float* attD1 = (const float*)d_in[5];
    const float* b1    = (const float*)d_in[6];
    const float* W2    = (const float*)d_in[7];
    const float* attS2 = (const float*)d_in[8];
    const float* attD2 = (const float*)d_in[9];
    const float* b2    = (const float*)d_in[10];
    const float* Wo    = (const float*)d_in[11];
    const float* bo    = (const float*)d_in[12];
    const float* Wg    = (const float*)d_in[13];
    const float* bg    = (const float*)d_in[14];
    const float* Wa    = (const float*)d_in[15];
    const float* ba    = (const float*)d_in[16];

    int n  = in_sizes[0] / 128;
    int E  = in_sizes[1] / 2;
    int ep = E + n;
    int nb = (n + SCAN_BLK - 1) / SCAN_BLK;

    // ---- CSR build (once; reused by both layers) ----
    deginit_kernel<<<(n + 255) / 256, 256>>>(n);
    hist_kernel<<<(E + 255) / 256, 256>>>(ei, E);
    scan1_kernel<<<nb, SCAN_BLK>>>(n);
    scan3_kernel<<<(n + 255) / 256, 256>>>(n);
    fill_kernel<<<(ep + 255) / 256, 256>>>(ei, E, ep);

    // ---- Layer 1 (GEMM writes fp16 h + att coefficients) ----
    gemm_kernel<128, false><<<(n + 63) / 64, 256>>>(x, W1, attS1, attD1, n);
    gat_node_kernel<<<((size_t)n * 32 + 255) / 256, 256>>>(b1, n);

    // ---- Layer 2 ----
    gemm_kernel<64, true><<<(n + 63) / 64, 256>>>(nullptr, W2, attS2, attD2, n);
    gat_node_kernel<<<((size_t)n * 32 + 255) / 256, 256>>>(b2, n);

    // ---- Pooling (binary search over sorted batch) ----
    poolsum_kernel<<<GMAX, 64>>>(batch, n);

    // ---- Heads ----
    heads_kernel<<<GMAX, 64>>>(Wo, bo, Wg, bg, Wa, ba, (float*)d_out);
}